// round 11
// baseline (speedup 1.0000x reference)
#include <cuda_runtime.h>

// PolynomialFlowRegularizer: B=64, C=2, H=512, W=512
// err_{b,c} = ( ||f||^2 - rhs^T G^{-1} rhs ) / N  ; out = sum_{b,c} err / B
// Fused kernel, wave-exact grid: 592 blocks = 148 SMs x 4 resident blocks.
// Channels 0..79 -> 5 chunks (13107 vecs), channels 80..127 -> 4 chunks (16384).

#define NCH 128                    // B*C
#define NPIX (512 * 512)           // 262144
#define VPC (NPIX / 4)             // 65536 float4 per channel
#define TPB 256
#define NBLK 592                   // 148 SMs * 4 blocks
#define N5CH 80                    // channels with 5 chunks (80*5 + 48*4 = 592)
#define MAXCK 5

// per-chunk partials: [channel][slot][7]; slot 4 of ch>=80 never written -> stays 0
__device__ float g_part[NCH * MAXCK * 7];
__device__ unsigned int g_count = 0;

// ---- compile-time closed-form G^{-1} pieces (grid symmetric, odd moments = 0) ----
constexpr double S0  = 512.0;
constexpr double hh  = 2.0 / 511.0;
constexpr double Si1 = 130816.0;
constexpr double Si2 = 44608256.0;
constexpr double Si3 = 17112825856.0;
constexpr double Si4 = 511.0 * 512.0 * 1023.0 * 784895.0 / 30.0;
constexpr double S2v = S0 - 2.0 * hh * Si1 + hh * hh * Si2;
constexpr double S4v = S0 - 4.0 * hh * Si1 + 6.0 * hh * hh * Si2
                      - 4.0 * hh * hh * hh * Si3 + hh * hh * hh * hh * Si4;
constexpr double Ga = S0 * S0, Gb = S0 * S2v, Gc = S0 * S4v, Gd = S2v * S2v;
constexpr double Gdet = (Gc - Gd) * (Ga * (Gc + Gd) - 2.0 * Gb * Gb);
constexpr double i00  = (Gc * Gc - Gd * Gd) / Gdet;
constexpr double i01  = -Gb * (Gc - Gd) / Gdet;
constexpr double i11  = (Ga * Gc - Gb * Gb) / Gdet;
constexpr double i12  = -(Ga * Gd - Gb * Gb) / Gdet;
constexpr double invXX  = 1.0 / (S0 * S2v);
constexpr double invXY  = 1.0 / (S2v * S2v);
constexpr double OUTSCL = 1.0 / ((double)NPIX * 64.0);

struct Acc { float s2, r0, r1, r2, r3, r4, r5; };

__device__ __forceinline__ void accum(Acc& a, float4 f, int vg) {  // vg: channel-local vec idx
    const float sc = 2.0f / 511.0f;
    const float yf  = fmaf((float)(vg >> 7), sc, -1.0f);        // row (128 vecs/row)
    const float xf0 = fmaf((float)((vg & 127) << 2), sc, -1.0f);
    const float xf1 = xf0 + sc;
    const float xf2 = xf1 + sc;
    const float xf3 = xf2 + sc;

    const float sf = (f.x + f.y) + (f.z + f.w);
    float sfx  = f.x * xf0;
    sfx = fmaf(f.y, xf1, sfx);
    sfx = fmaf(f.z, xf2, sfx);
    sfx = fmaf(f.w, xf3, sfx);
    float sfx2 = f.x * xf0 * xf0;
    sfx2 = fmaf(f.y * xf1, xf1, sfx2);
    sfx2 = fmaf(f.z * xf2, xf2, sfx2);
    sfx2 = fmaf(f.w * xf3, xf3, sfx2);

    a.s2 = fmaf(f.x, f.x, a.s2);
    a.s2 = fmaf(f.y, f.y, a.s2);
    a.s2 = fmaf(f.z, f.z, a.s2);
    a.s2 = fmaf(f.w, f.w, a.s2);

    a.r0 += sf;
    a.r1 += sfx;
    a.r2 = fmaf(sf, yf, a.r2);
    a.r3 += sfx2;
    a.r4 = fmaf(sfx, yf, a.r4);
    a.r5 = fmaf(sf * yf, yf, a.r5);
}

__global__ __launch_bounds__(TPB, 4) void pfr_fused(const float4* __restrict__ in,
                                                    float* __restrict__ out) {
    const int bid = blockIdx.x;     // 0..591
    const int t   = threadIdx.x;

    // bid -> (channel, slot, chunk-range)
    int ch, idx, nck;
    if (bid < N5CH * 5) { ch = bid / 5;              idx = bid % 5;          nck = 5; }
    else                { ch = N5CH + (bid - 400)/4; idx = (bid - 400) % 4;  nck = 4; }
    const int s = (idx * VPC) / nck;        // channel-local [s, e)
    const int e = ((idx + 1) * VPC) / nck;

    const float4* base = in + (size_t)ch * VPC;
    Acc a = {0.f, 0.f, 0.f, 0.f, 0.f, 0.f, 0.f};

    const int n  = e - s;
    const int nb = n / (4 * TPB);           // full MLP=4 batches
    for (int k = 0; k < nb; k++) {
        const int v0 = s + k * (4 * TPB) + t;
        float4 f0 = __ldcs(&base[v0 + 0 * TPB]);   // front-batched: explicit MLP=4
        float4 f1 = __ldcs(&base[v0 + 1 * TPB]);
        float4 f2 = __ldcs(&base[v0 + 2 * TPB]);
        float4 f3 = __ldcs(&base[v0 + 3 * TPB]);
        accum(a, f0, v0 + 0 * TPB);
        accum(a, f1, v0 + 1 * TPB);
        accum(a, f2, v0 + 2 * TPB);
        accum(a, f3, v0 + 3 * TPB);
    }
    // remainder (non-multiple chunk lengths for nck=5)
    for (int v = s + nb * (4 * TPB) + t; v < e; v += TPB)
        accum(a, __ldcs(&base[v]), v);

    // ---- block-local deterministic reduction ----
    float vals[7] = {a.s2, a.r0, a.r1, a.r2, a.r3, a.r4, a.r5};
#pragma unroll
    for (int i = 0; i < 7; i++) {
#pragma unroll
        for (int off = 16; off > 0; off >>= 1)
            vals[i] += __shfl_down_sync(0xFFFFFFFFu, vals[i], off);
    }

    __shared__ float sh[8][7];
    const int warp = t >> 5;
    const int lane = t & 31;
    if (lane == 0) {
#pragma unroll
        for (int i = 0; i < 7; i++) sh[warp][i] = vals[i];
    }
    __syncthreads();

    if (t == 0) {
        float* dst = &g_part[((size_t)ch * MAXCK + idx) * 7];
#pragma unroll
        for (int i = 0; i < 7; i++) {
            float sum = sh[0][i];
#pragma unroll
            for (int w = 1; w < 8; w++) sum += sh[w][i];
            dst[i] = sum;
        }
    }

    // ---- last-block finalize (threadfence-reduction pattern) ----
    __shared__ bool amLast;
    __threadfence();
    if (t == 0)
        amLast = (atomicAdd(&g_count, 1u) == NBLK - 1);
    __syncthreads();
    if (!amLast) return;

    if (t == 0) g_count = 0;        // reset for next graph replay
    __threadfence();

    // one thread per channel: fold up to 5 slot-partials (unused slots are 0.0)
    double err = 0.0;
    if (t < NCH) {
        double s7[7] = {0, 0, 0, 0, 0, 0, 0};
#pragma unroll
        for (int cc = 0; cc < MAXCK; cc++) {
            const float* p = &g_part[((size_t)t * MAXCK + cc) * 7];
#pragma unroll
            for (int i = 0; i < 7; i++) s7[i] += (double)__ldcg(&p[i]);
        }
        const double m0 = s7[1], mx = s7[2], my = s7[3], mxx = s7[4], mxy = s7[5], myy = s7[6];
        double quad = (mx * mx + my * my) * invXX + mxy * mxy * invXY;
        quad += i00 * m0 * m0 + 2.0 * i01 * m0 * (mxx + myy)
              + i11 * (mxx * mxx + myy * myy) + 2.0 * i12 * mxx * myy;
        err = s7[0] - quad;
    }

    // deterministic tree reduction across 128 channels
#pragma unroll
    for (int off = 16; off > 0; off >>= 1)
        err += __shfl_down_sync(0xFFFFFFFFu, err, off);

    __shared__ double wsum[4];
    if (lane == 0 && warp < 4) wsum[warp] = err;
    __syncthreads();

    if (t == 0) {
        double total = wsum[0] + wsum[1] + wsum[2] + wsum[3];
        out[0] = (float)(total * OUTSCL);
    }
}

extern "C" void kernel_launch(void* const* d_in, const int* in_sizes, int n_in,
                              void* d_out, int out_size) {
    (void)in_sizes; (void)n_in; (void)out_size;
    const float4* in = (const float4*)d_in[0];
    float* out = (float*)d_out;
    pfr_fused<<<NBLK, TPB>>>(in, out);
}

// round 12
// speedup vs baseline: 1.0526x; 1.0526x over previous
#include <cuda_runtime.h>

// PolynomialFlowRegularizer: B=64, C=2, H=512, W=512
// err_{b,c} = ( ||f||^2 - rhs^T G^{-1} rhs ) / N  ; out = sum_{b,c} err / B
// Fused kernel: explicit 4-wide MLP streaming + last-block closed-form finalize.
// R9 config exactly, minus __ldcs (A/B: evict-first policy suspected of killing stream BW).

#define NCH 128                    // B*C = 64*2
#define NPIX (512 * 512)           // 262144
#define CHUNKS 4                   // blocks per channel
#define TPB 256
#define VPC (NPIX / 4)             // 65536 float4 per channel
#define VECS_PER_CHUNK (VPC / CHUNKS)           // 16384
#define BATCHES (VECS_PER_CHUNK / (4 * TPB))    // 16 batches of 4 vecs/thread
#define TOTAL_BLOCKS (CHUNKS * NCH)             // 512

// per-block partials: [channel][chunk][7] ; 7 = {s2, r0..r5}
__device__ float g_part[NCH * CHUNKS * 7];
__device__ unsigned int g_count = 0;

// ---- compile-time closed-form G^{-1} pieces (grid symmetric, odd moments = 0) ----
constexpr double S0  = 512.0;
constexpr double hh  = 2.0 / 511.0;
constexpr double Si1 = 130816.0;
constexpr double Si2 = 44608256.0;
constexpr double Si3 = 17112825856.0;
constexpr double Si4 = 511.0 * 512.0 * 1023.0 * 784895.0 / 30.0;
constexpr double S2v = S0 - 2.0 * hh * Si1 + hh * hh * Si2;
constexpr double S4v = S0 - 4.0 * hh * Si1 + 6.0 * hh * hh * Si2
                      - 4.0 * hh * hh * hh * Si3 + hh * hh * hh * hh * Si4;
constexpr double Ga = S0 * S0, Gb = S0 * S2v, Gc = S0 * S4v, Gd = S2v * S2v;
constexpr double Gdet = (Gc - Gd) * (Ga * (Gc + Gd) - 2.0 * Gb * Gb);
constexpr double i00  = (Gc * Gc - Gd * Gd) / Gdet;
constexpr double i01  = -Gb * (Gc - Gd) / Gdet;
constexpr double i11  = (Ga * Gc - Gb * Gb) / Gdet;
constexpr double i12  = -(Ga * Gd - Gb * Gb) / Gdet;
constexpr double invXX  = 1.0 / (S0 * S2v);
constexpr double invXY  = 1.0 / (S2v * S2v);
constexpr double OUTSCL = 1.0 / ((double)NPIX * 64.0);

struct Acc { float s2, r0, r1, r2, r3, r4, r5; };

__device__ __forceinline__ void accum(Acc& a, float4 f, int vg) {
    const float sc = 2.0f / 511.0f;
    const float yf  = fmaf((float)(vg >> 7), sc, -1.0f);        // row (128 vecs/row)
    const float xf0 = fmaf((float)((vg & 127) << 2), sc, -1.0f);
    const float xf1 = xf0 + sc;
    const float xf2 = xf1 + sc;
    const float xf3 = xf2 + sc;

    const float sf = (f.x + f.y) + (f.z + f.w);
    float sfx  = f.x * xf0;
    sfx = fmaf(f.y, xf1, sfx);
    sfx = fmaf(f.z, xf2, sfx);
    sfx = fmaf(f.w, xf3, sfx);
    float sfx2 = f.x * xf0 * xf0;
    sfx2 = fmaf(f.y * xf1, xf1, sfx2);
    sfx2 = fmaf(f.z * xf2, xf2, sfx2);
    sfx2 = fmaf(f.w * xf3, xf3, sfx2);

    a.s2 = fmaf(f.x, f.x, a.s2);
    a.s2 = fmaf(f.y, f.y, a.s2);
    a.s2 = fmaf(f.z, f.z, a.s2);
    a.s2 = fmaf(f.w, f.w, a.s2);

    a.r0 += sf;
    a.r1 += sfx;
    a.r2 = fmaf(sf, yf, a.r2);
    a.r3 += sfx2;
    a.r4 = fmaf(sfx, yf, a.r4);
    a.r5 = fmaf(sf * yf, yf, a.r5);
}

__global__ __launch_bounds__(TPB) void pfr_fused(const float4* __restrict__ in,
                                                 float* __restrict__ out) {
    const int chunk = blockIdx.x;   // 0..CHUNKS-1
    const int bc    = blockIdx.y;   // 0..NCH-1
    const int t     = threadIdx.x;

    const float4* base = in + (size_t)bc * VPC + (size_t)chunk * VECS_PER_CHUNK;
    Acc a = {0.f, 0.f, 0.f, 0.f, 0.f, 0.f, 0.f};

#pragma unroll 4
    for (int k = 0; k < BATCHES; k++) {
        const int v0 = k * (4 * TPB) + t;        // 4 loads, stride TPB apart
        // front-batched plain loads (default cache policy): explicit MLP=4
        float4 f0 = base[v0 + 0 * TPB];
        float4 f1 = base[v0 + 1 * TPB];
        float4 f2 = base[v0 + 2 * TPB];
        float4 f3 = base[v0 + 3 * TPB];

        const int vg0 = chunk * VECS_PER_CHUNK + v0;
        accum(a, f0, vg0 + 0 * TPB);
        accum(a, f1, vg0 + 1 * TPB);
        accum(a, f2, vg0 + 2 * TPB);
        accum(a, f3, vg0 + 3 * TPB);
    }

    // ---- block-local deterministic reduction ----
    float vals[7] = {a.s2, a.r0, a.r1, a.r2, a.r3, a.r4, a.r5};
#pragma unroll
    for (int i = 0; i < 7; i++) {
#pragma unroll
        for (int off = 16; off > 0; off >>= 1)
            vals[i] += __shfl_down_sync(0xFFFFFFFFu, vals[i], off);
    }

    __shared__ float sh[8][7];  // 8 warps
    const int warp = t >> 5;
    const int lane = t & 31;
    if (lane == 0) {
#pragma unroll
        for (int i = 0; i < 7; i++) sh[warp][i] = vals[i];
    }
    __syncthreads();

    if (t == 0) {
        float* dst = &g_part[((size_t)bc * CHUNKS + chunk) * 7];
#pragma unroll
        for (int i = 0; i < 7; i++) {
            float s = sh[0][i];
#pragma unroll
            for (int w = 1; w < 8; w++) s += sh[w][i];
            dst[i] = s;
        }
    }

    // ---- last-block finalize (threadfence-reduction pattern) ----
    __shared__ bool amLast;
    __threadfence();
    if (t == 0)
        amLast = (atomicAdd(&g_count, 1u) == TOTAL_BLOCKS - 1);
    __syncthreads();
    if (!amLast) return;

    if (t == 0) g_count = 0;         // reset for next graph replay
    __threadfence();

    // one thread per channel: fold 4 chunk-partials in double
    double err = 0.0;
    if (t < NCH) {
        double s[7] = {0, 0, 0, 0, 0, 0, 0};
#pragma unroll
        for (int cc = 0; cc < CHUNKS; cc++) {
            const float* p = &g_part[((size_t)t * CHUNKS + cc) * 7];
#pragma unroll
            for (int i = 0; i < 7; i++) s[i] += (double)__ldcg(&p[i]);
        }
        const double m0 = s[1], mx = s[2], my = s[3], mxx = s[4], mxy = s[5], myy = s[6];
        double quad = (mx * mx + my * my) * invXX + mxy * mxy * invXY;
        quad += i00 * m0 * m0 + 2.0 * i01 * m0 * (mxx + myy)
              + i11 * (mxx * mxx + myy * myy) + 2.0 * i12 * mxx * myy;
        err = s[0] - quad;
    }

    // deterministic tree reduction across 128 channels
#pragma unroll
    for (int off = 16; off > 0; off >>= 1)
        err += __shfl_down_sync(0xFFFFFFFFu, err, off);

    __shared__ double wsum[4];
    if (lane == 0 && warp < 4) wsum[warp] = err;
    __syncthreads();

    if (t == 0) {
        double total = wsum[0] + wsum[1] + wsum[2] + wsum[3];
        out[0] = (float)(total * OUTSCL);
    }
}

extern "C" void kernel_launch(void* const* d_in, const int* in_sizes, int n_in,
                              void* d_out, int out_size) {
    (void)in_sizes; (void)n_in; (void)out_size;
    const float4* in = (const float4*)d_in[0];
    float* out = (float*)d_out;
    pfr_fused<<<dim3(CHUNKS, NCH), TPB>>>(in, out);
}